// round 7
// baseline (speedup 1.0000x reference)
#include <cuda_runtime.h>
#include <math.h>

// ---------------- problem constants ----------------
#define BATCH   1024
#define TTREES  34
#define EMB     128

#define R0 278528   // level-0 nodes: B*T*8
#define R1 139264
#define R2 69632
#define R3 34816    // = B*T (roots)
#define RF 9216     // leaf-MLP rows: B*9

// idx segment offsets (ints)
#define IDX0 0
#define IDX1 (4*R0)
#define IDX2 (IDX1 + 4*R1)
#define IDX3 (IDX2 + 4*R2)
#define IDXF (IDX3 + 4*R3)
#define IDXTOT (IDXF + 3*RF)

// ---------------- device scratch (allocation-free rule: __device__ globals) ----------------
__device__ float g_H[R0 * 256];        // MLP hidden buffer (max: level0, 285MB; leaf needs 9216*512)
__device__ float g_o0[R0 * 128];       // level0 out  (= level1 input viewed as (R1,256))
__device__ float g_o1[R1 * 128];
__device__ float g_o2[R2 * 128];
__device__ float g_roots[R3 * 128];
__device__ float g_pairs[RF * 256];
__device__ float g_stmt[RF * 128];
__device__ int   g_idx[IDXTOT];
__device__ int   g_counts[24];

// ---------------- zero the per-stage expert counters ----------------
__global__ void k_zero_counts(int* c) {
    if (threadIdx.x < 24) c[threadIdx.x] = 0;
}

// ---------------- build per-expert row lists (warp-aggregated atomics) ----------------
// id for row r = ids[(r/npt)*stride + off + (r%npt)]
__global__ void k_build_idx(const int* __restrict__ ids, int n_rows, int npt, int off,
                            int stride, int* __restrict__ counts, int* __restrict__ idx,
                            int seg, int n_exp)
{
    int r = blockIdx.x * blockDim.x + threadIdx.x;
    bool v = (r < n_rows);
    int id = -1;
    if (v) id = ids[(r / npt) * stride + off + (r % npt)];
    unsigned lane = threadIdx.x & 31;
    for (int e = 0; e < n_exp; e++) {
        unsigned m = __ballot_sync(0xffffffffu, v && (id == e));
        if (v && (id == e)) {
            int leader = __ffs(m) - 1;
            int base = 0;
            if ((int)lane == leader) base = atomicAdd(&counts[e], __popc(m));
            base = __shfl_sync(m, base, leader);
            int pos = base + __popc(m & ((1u << lane) - 1u));
            idx[(size_t)e * seg + pos] = r;
        }
    }
}

// ---------------- grouped expert GEMM with row gather/scatter ----------------
// Y[r, n0:n0+128] = act( X[r, :] @ W[e] + b[e] ) for rows r in expert-e bucket.
// If g2 != nullptr (level 0): X row r col c = emb[ g2[2r + c/128] ][ c%128 ]  (X := ent_emb).
// CTA: 64 rows x 128 cols, 256 threads, 4x8 micro-tile, K-chunks of 16.
__global__ __launch_bounds__(256) void k_expert_gemm(
    const float* __restrict__ X, const int* __restrict__ g2,
    const float* __restrict__ Wg, const float* __restrict__ Bg,
    float* __restrict__ Y,
    const int* __restrict__ row_idx, const int* __restrict__ counts,
    int seg, int K, int N, int relu)
{
    const int e   = blockIdx.y;
    const int cnt = counts[e];
    const int m0  = blockIdx.x * 64;
    if (m0 >= cnt) return;
    const int n0  = blockIdx.z * 128;

    const float* W    = Wg + (size_t)e * K * N;
    const float* bias = Bg + (size_t)e * N;

    __shared__ float Xs[16][68];     // [k][m], padded
    __shared__ float Ws[16][128];    // [k][n]
    __shared__ int   ridx[64];

    const int tid = threadIdx.x;
    int valid = cnt - m0; if (valid > 64) valid = 64;
    if (tid < 64) {
        int mm = (tid < valid) ? tid : (valid - 1);   // clamp (duplicates never stored)
        ridx[tid] = row_idx[(size_t)e * seg + m0 + mm];
    }
    __syncthreads();

    const int tx = tid & 15;          // col group: cols tx*8 .. tx*8+7
    const int ty = tid >> 4;          // row group: rows ty*4 .. ty*4+3
    const int xm = tid >> 2;          // Xs loader: row 0..63
    const int xc = (tid & 3) << 2;    // Xs loader: col chunk {0,4,8,12}
    const int rX = ridx[xm];
    const int ka = tid >> 5;          // Ws loader k rows: ka and ka+8
    const int ca = (tid & 31) << 2;   // Ws loader col

    float acc[4][8];
    #pragma unroll
    for (int i = 0; i < 4; i++)
        #pragma unroll
        for (int j = 0; j < 8; j++) acc[i][j] = 0.f;

    for (int k0 = 0; k0 < K; k0 += 16) {
        float4 xv;
        if (g2) {
            int col = k0 + xc;
            int src = __ldg(&g2[((size_t)rX << 1) + (col >> 7)]);
            xv = *(const float4*)(X + ((size_t)src << 7) + (col & 127));
        } else {
            xv = *(const float4*)(X + (size_t)rX * K + k0 + xc);
        }
        float4 wv0 = *(const float4*)(W + (size_t)(k0 + ka)     * N + n0 + ca);
        float4 wv1 = *(const float4*)(W + (size_t)(k0 + ka + 8) * N + n0 + ca);
        __syncthreads();   // previous chunk's smem reads done
        Xs[xc + 0][xm] = xv.x;
        Xs[xc + 1][xm] = xv.y;
        Xs[xc + 2][xm] = xv.z;
        Xs[xc + 3][xm] = xv.w;
        *(float4*)&Ws[ka][ca]     = wv0;
        *(float4*)&Ws[ka + 8][ca] = wv1;
        __syncthreads();
        #pragma unroll
        for (int kk = 0; kk < 16; kk++) {
            float4 a  = *(const float4*)&Xs[kk][ty << 2];
            float4 b0 = *(const float4*)&Ws[kk][tx << 3];
            float4 b1 = *(const float4*)&Ws[kk][(tx << 3) + 4];
            float av[4] = {a.x, a.y, a.z, a.w};
            float bv[8] = {b0.x, b0.y, b0.z, b0.w, b1.x, b1.y, b1.z, b1.w};
            #pragma unroll
            for (int i = 0; i < 4; i++)
                #pragma unroll
                for (int j = 0; j < 8; j++)
                    acc[i][j] = fmaf(av[i], bv[j], acc[i][j]);
        }
    }

    float4 bb0 = *(const float4*)(bias + n0 + (tx << 3));
    float4 bb1 = *(const float4*)(bias + n0 + (tx << 3) + 4);
    const float bz[8] = {bb0.x, bb0.y, bb0.z, bb0.w, bb1.x, bb1.y, bb1.z, bb1.w};
    #pragma unroll
    for (int i = 0; i < 4; i++) {
        int m = (ty << 2) + i;
        if (m < valid) {
            int r = ridx[m];
            float o[8];
            #pragma unroll
            for (int j = 0; j < 8; j++) {
                o[j] = acc[i][j] + bz[j];
                if (relu) o[j] = fmaxf(o[j], 0.f);
            }
            float4 s0 = {o[0], o[1], o[2], o[3]};
            float4 s1 = {o[4], o[5], o[6], o[7]};
            float* yp = Y + (size_t)r * N + n0 + (tx << 3);
            *(float4*)yp       = s0;
            *(float4*)(yp + 4) = s1;
        }
    }
}

// ---------------- gather statement pairs from roots ----------------
// pairs[r=(b,p), 0:256] = roots rows (b*34+16+2p, b*34+16+2p+1) — contiguous in memory.
__global__ void k_pairs(const float* __restrict__ roots, float* __restrict__ pairs)
{
    int i = blockIdx.x * blockDim.x + threadIdx.x;   // float4 index
    if (i >= RF * 64) return;
    int r  = i >> 6;
    int c4 = i & 63;
    int b = r / 9, p = r % 9;
    ((float4*)pairs)[i] = ((const float4*)roots)[((size_t)(b * 17 + 8 + p) << 6) + c4];
}

// ---------------- final: 3 q-projections + softmax attends + concat ----------------
__global__ void k_finale(const float* __restrict__ roots, const float* __restrict__ stmt,
                         const float* __restrict__ th_emb, const int* __restrict__ th_idx,
                         const float* __restrict__ heW, const float* __restrict__ heb,
                         const float* __restrict__ hgW, const float* __restrict__ hgb,
                         const float* __restrict__ htW, const float* __restrict__ htb,
                         float* __restrict__ out)
{
    __shared__ float obj[128];
    __shared__ float q[128];
    __shared__ float keys[16][128];
    __shared__ float aw[16];
    const int b = blockIdx.x;
    const int t = threadIdx.x;

    float ov = stmt[(size_t)(b * 9 + 8) * 128 + t];
    obj[t] = ov;
    out[(size_t)b * 512 + t] = ov;                    // concat slot 0: obj
    __syncthreads();

    const float* Wq[3] = {heW, hgW, htW};
    const float* bq[3] = {heb, hgb, htb};
    const int    nk[3] = {16, 8, 8};
    const int    oo[3] = {256, 128, 384};             // ent_ctx @256, gt_ctx @128, th_ctx @384

    for (int s = 0; s < 3; s++) {
        float accq = bq[s][t];
        const float* w = Wq[s];
        #pragma unroll 4
        for (int k = 0; k < 128; k++) accq = fmaf(obj[k], w[k * 128 + t], accq);
        q[t] = accq;
        if (s == 0) {
            for (int j = 0; j < 16; j++) keys[j][t] = roots[(size_t)(b * 34 + j) * 128 + t];
        } else if (s == 1) {
            for (int j = 0; j < 8; j++)  keys[j][t] = stmt[(size_t)(b * 9 + j) * 128 + t];
        } else {
            for (int j = 0; j < 8; j++)  keys[j][t] = th_emb[(size_t)th_idx[b * 8 + j] * 128 + t];
        }
        __syncthreads();
        int n = nk[s];
        if (t < n) {
            float sdot = 0.f;
            for (int k = 0; k < 128; k++) sdot = fmaf(keys[t][k], q[k], sdot);
            aw[t] = sdot;
        }
        __syncthreads();
        if (t == 0) {
            float mx = aw[0];
            for (int j = 1; j < n; j++) mx = fmaxf(mx, aw[j]);
            float sm = 0.f;
            for (int j = 0; j < n; j++) { float ev = expf(aw[j] - mx); aw[j] = ev; sm += ev; }
            float inv = 1.f / sm;
            for (int j = 0; j < n; j++) aw[j] *= inv;
        }
        __syncthreads();
        float ctx = 0.f;
        for (int j = 0; j < n; j++) ctx = fmaf(aw[j], keys[j][t], ctx);
        out[(size_t)b * 512 + oo[s] + t] = ctx;
        __syncthreads();   // keys/aw reused next section
    }
}

// ---------------- launch ----------------
extern "C" void kernel_launch(void* const* d_in, const int* in_sizes, int n_in,
                              void* d_out, int out_size)
{
    const int*   leaf_idx = (const int*)  d_in[0];
    const int*   nf_ids   = (const int*)  d_in[1];
    const int*   lf_ids   = (const int*)  d_in[2];
    const int*   th_idx   = (const int*)  d_in[3];
    const float* ent_emb  = (const float*)d_in[4];
    const float* th_emb   = (const float*)d_in[5];
    const float* nfW1     = (const float*)d_in[6];
    const float* nfb1     = (const float*)d_in[7];
    const float* nfW2     = (const float*)d_in[8];
    const float* nfb2     = (const float*)d_in[9];
    const float* lfW1     = (const float*)d_in[10];
    const float* lfb1     = (const float*)d_in[11];
    const float* lfW2     = (const float*)d_in[12];
    const float* lfb2     = (const float*)d_in[13];
    const float* heW      = (const float*)d_in[14];
    const float* heb      = (const float*)d_in[15];
    const float* hgW      = (const float*)d_in[16];
    const float* hgb      = (const float*)d_in[17];
    const float* htW      = (const float*)d_in[18];
    const float* htb      = (const float*)d_in[19];
    float* out = (float*)d_out;

    void *pH, *po0, *po1, *po2, *proots, *ppairs, *pstmt, *pidx, *pcnt;
    cudaGetSymbolAddress(&pH,     g_H);
    cudaGetSymbolAddress(&po0,    g_o0);
    cudaGetSymbolAddress(&po1,    g_o1);
    cudaGetSymbolAddress(&po2,    g_o2);
    cudaGetSymbolAddress(&proots, g_roots);
    cudaGetSymbolAddress(&ppairs, g_pairs);
    cudaGetSymbolAddress(&pstmt,  g_stmt);
    cudaGetSymbolAddress(&pidx,   g_idx);
    cudaGetSymbolAddress(&pcnt,   g_counts);
    float* H     = (float*)pH;
    float* o0    = (float*)po0;
    float* o1    = (float*)po1;
    float* o2    = (float*)po2;
    float* roots = (float*)proots;
    float* pairs = (float*)ppairs;
    float* stmt  = (float*)pstmt;
    int*   idx   = (int*)pidx;
    int*   cnt   = (int*)pcnt;

    // 1) counters + per-expert row lists (input-only, run up front)
    k_zero_counts<<<1, 32>>>(cnt);
    k_build_idx<<<R0 / 256, 256>>>(nf_ids, R0, 8, 0,  15, cnt + 0,  idx + IDX0, R0, 4);
    k_build_idx<<<R1 / 256, 256>>>(nf_ids, R1, 4, 8,  15, cnt + 4,  idx + IDX1, R1, 4);
    k_build_idx<<<R2 / 256, 256>>>(nf_ids, R2, 2, 12, 15, cnt + 8,  idx + IDX2, R2, 4);
    k_build_idx<<<R3 / 256, 256>>>(nf_ids, R3, 1, 14, 15, cnt + 12, idx + IDX3, R3, 4);
    k_build_idx<<<RF / 256, 256>>>(lf_ids, RF, 9, 0,  9,  cnt + 16, idx + IDXF, RF, 3);

    // 2) tree levels (layer1 relu -> H, layer2 -> level output)
    // level 0: input gathered from ent_emb via leaf_idx (g2 path)
    k_expert_gemm<<<dim3(R0/64, 4, 2), 256>>>(ent_emb, leaf_idx, nfW1, nfb1, H,  idx+IDX0, cnt+0,  R0, 256, 256, 1);
    k_expert_gemm<<<dim3(R0/64, 4, 1), 256>>>(H, nullptr,        nfW2, nfb2, o0, idx+IDX0, cnt+0,  R0, 256, 128, 0);
    k_expert_gemm<<<dim3(R1/64, 4, 2), 256>>>(o0, nullptr,       nfW1, nfb1, H,  idx+IDX1, cnt+4,  R1, 256, 256, 1);
    k_expert_gemm<<<dim3(R1/64, 4, 1), 256>>>(H, nullptr,        nfW2, nfb2, o1, idx+IDX1, cnt+4,  R1, 256, 128, 0);
    k_expert_gemm<<<dim3(R2/64, 4, 2), 256>>>(o1, nullptr,       nfW1, nfb1, H,  idx+IDX2, cnt+8,  R2, 256, 256, 1);
    k_expert_gemm<<<dim3(R2/64, 4, 1), 256>>>(H, nullptr,        nfW2, nfb2, o2, idx+IDX2, cnt+8,  R2, 256, 128, 0);
    k_expert_gemm<<<dim3(R3/64, 4, 2), 256>>>(o2, nullptr,       nfW1, nfb1, H,  idx+IDX3, cnt+12, R3, 256, 256, 1);
    k_expert_gemm<<<dim3(R3/64, 4, 1), 256>>>(H, nullptr,        nfW2, nfb2, roots, idx+IDX3, cnt+12, R3, 256, 128, 0);

    // 3) statement MLP on root pairs
    k_pairs<<<(RF * 64 + 255) / 256, 256>>>(roots, pairs);
    k_expert_gemm<<<dim3(RF/64, 3, 4), 256>>>(pairs, nullptr, lfW1, lfb1, H,    idx+IDXF, cnt+16, RF, 256, 512, 1);
    k_expert_gemm<<<dim3(RF/64, 3, 1), 256>>>(H, nullptr,     lfW2, lfb2, stmt, idx+IDXF, cnt+16, RF, 512, 128, 0);

    // 4) attention heads + concat
    k_finale<<<BATCH, 128>>>(roots, stmt, th_emb, th_idx, heW, heb, hgW, hgb, htW, htb, out);
}

// round 12
// speedup vs baseline: 2.0841x; 2.0841x over previous
#include <cuda_runtime.h>
#include <cuda_bf16.h>
#include <math.h>
#include <stdint.h>

// ---------------- problem constants ----------------
#define BATCH   1024
#define R0 278528   // level-0 nodes: B*T*8
#define R1 139264
#define R2 69632
#define R3 34816    // = B*T (roots)
#define RF 9216     // leaf-MLP rows: B*9

// idx segment offsets (ints)
#define IDX0 0
#define IDX1 (4*R0)
#define IDX2 (IDX1 + 4*R1)
#define IDX3 (IDX2 + 4*R2)
#define IDXF (IDX3 + 4*R3)
#define IDXTOT (IDXF + 3*RF)

// ---------------- device scratch (allocation-free rule: __device__ globals) ----------------
__device__ __align__(16) __nv_bfloat16 g_Hhi[(size_t)R0*256];   // hidden; also leaf hidden [RF][512]
__device__ __align__(16) __nv_bfloat16 g_Hlo[(size_t)R0*256];
__device__ __align__(16) __nv_bfloat16 g_o0hi[(size_t)R0*128];
__device__ __align__(16) __nv_bfloat16 g_o0lo[(size_t)R0*128];
__device__ __align__(16) __nv_bfloat16 g_o1hi[(size_t)R1*128];
__device__ __align__(16) __nv_bfloat16 g_o1lo[(size_t)R1*128];
__device__ __align__(16) __nv_bfloat16 g_o2hi[(size_t)R2*128];
__device__ __align__(16) __nv_bfloat16 g_o2lo[(size_t)R2*128];
__device__ __align__(16) __nv_bfloat16 g_rthi[(size_t)R3*128];
__device__ __align__(16) __nv_bfloat16 g_rtlo[(size_t)R3*128];
__device__ __align__(16) float         g_roots[(size_t)R3*128];
__device__ __align__(16) __nv_bfloat16 g_sthi[(size_t)RF*128];
__device__ __align__(16) __nv_bfloat16 g_stlo[(size_t)RF*128];
__device__ __align__(16) float         g_stmt[(size_t)RF*128];
__device__ __align__(16) __nv_bfloat16 g_ehi[2000*128];
__device__ __align__(16) __nv_bfloat16 g_elo[2000*128];
// transposed split weights: [e][N][K]  (== col-major B for mma row.col)
__device__ __align__(16) __nv_bfloat16 g_w1hi[4*256*256];
__device__ __align__(16) __nv_bfloat16 g_w1lo[4*256*256];
__device__ __align__(16) __nv_bfloat16 g_w2hi[4*128*256];
__device__ __align__(16) __nv_bfloat16 g_w2lo[4*128*256];
__device__ __align__(16) __nv_bfloat16 g_l1hi[3*512*256];
__device__ __align__(16) __nv_bfloat16 g_l1lo[3*512*256];
__device__ __align__(16) __nv_bfloat16 g_l2hi[3*128*512];
__device__ __align__(16) __nv_bfloat16 g_l2lo[3*128*512];
__device__ int   g_idx[IDXTOT];
__device__ int   g_counts[24];

// ---------------- PTX helpers (sm_80-level only; portable to sm_103 target) ----------------
__device__ __forceinline__ uint32_t s2u(const void* p) {
    uint32_t a;
    asm("{ .reg .u64 t; cvta.to.shared.u64 t, %1; cvt.u32.u64 %0, t; }" : "=r"(a) : "l"(p));
    return a;
}
__device__ __forceinline__ void cpa16(uint32_t d, const void* s) {
    asm volatile("cp.async.cg.shared.global [%0], [%1], 16;" :: "r"(d), "l"(s));
}
__device__ __forceinline__ void ldm_x4(uint32_t* r, uint32_t addr) {
    asm volatile("ldmatrix.sync.aligned.m8n8.x4.shared.b16 {%0,%1,%2,%3}, [%4];"
        : "=r"(r[0]), "=r"(r[1]), "=r"(r[2]), "=r"(r[3]) : "r"(addr));
}
__device__ __forceinline__ void mma_bf16(float* c, const uint32_t* a, const uint32_t* b) {
    asm volatile("mma.sync.aligned.m16n8k16.row.col.f32.bf16.bf16.f32 "
        "{%0,%1,%2,%3}, {%4,%5,%6,%7}, {%8,%9}, {%0,%1,%2,%3};"
        : "+f"(c[0]), "+f"(c[1]), "+f"(c[2]), "+f"(c[3])
        : "r"(a[0]), "r"(a[1]), "r"(a[2]), "r"(a[3]), "r"(b[0]), "r"(b[1]));
}

// smem layout: A tiles [2 stage][2 part] of 128 rows x 16 bf16 (stride 24 elem = 48B) = 6144B each
// then B tiles same; ridx at 49152.
#define ST_A(s,p)  ((uint32_t)(((s)*2+(p))*6144))
#define ST_B(s,p)  ((uint32_t)(24576 + ((s)*2+(p))*6144))
#define S_RIDX 49152
#define SMEM_BYTES 49664

// ---------------- zero counters ----------------
__global__ void k_zero_counts(int* c) { if (threadIdx.x < 24) c[threadIdx.x] = 0; }

// ---------------- build per-expert row lists ----------------
__global__ void k_build_idx(const int* __restrict__ ids, int n_rows, int npt, int off,
                            int stride, int* __restrict__ counts, int* __restrict__ idx,
                            int seg, int n_exp)
{
    int r = blockIdx.x * blockDim.x + threadIdx.x;
    bool v = (r < n_rows);
    int id = -1;
    if (v) id = ids[(r / npt) * stride + off + (r % npt)];
    unsigned lane = threadIdx.x & 31;
    for (int e = 0; e < n_exp; e++) {
        unsigned m = __ballot_sync(0xffffffffu, v && (id == e));
        if (v && (id == e)) {
            int leader = __ffs(m) - 1;
            int base = 0;
            if ((int)lane == leader) base = atomicAdd(&counts[e], __popc(m));
            base = __shfl_sync(m, base, leader);
            int pos = base + __popc(m & ((1u << lane) - 1u));
            idx[(size_t)e * seg + pos] = r;
        }
    }
}

// ---------------- fp32 -> bf16 hi/lo split ----------------
__global__ void k_split(const float* __restrict__ s, __nv_bfloat16* __restrict__ hi,
                        __nv_bfloat16* __restrict__ lo, int n)
{
    int i = blockIdx.x * blockDim.x + threadIdx.x;
    if (i >= n) return;
    float v = s[i];
    __nv_bfloat16 h = __float2bfloat16(v);
    hi[i] = h;
    lo[i] = __float2bfloat16(v - __bfloat162float(h));
}

// ---------------- transpose + split weights: src [e][K][N] -> dst [e][N][K] ----------------
__global__ void k_prep_w(const float* __restrict__ src, __nv_bfloat16* __restrict__ hi,
                         __nv_bfloat16* __restrict__ lo, int K, int N, int total)
{
    int i = blockIdx.x * blockDim.x + threadIdx.x;
    if (i >= total) return;
    int k = i % K;
    int n = (i / K) % N;
    int e = i / (K * N);
    float v = src[((size_t)e * K + k) * N + n];
    __nv_bfloat16 h = __float2bfloat16(v);
    hi[i] = h;
    lo[i] = __float2bfloat16(v - __bfloat162float(h));
}

// ---------------- grouped expert GEMM on mma.sync bf16 (hi/lo split, fp32 accum) ----------------
// Y[r, n0:n0+128] = act( X[r,:] @ W[e]^T + b[e] ), rows from expert bucket.
// mode: 0 normal, 1 gather via g2/ent_emb (level 0), 2 pair-map into roots (leaf stage).
__global__ __launch_bounds__(256) void k_mma_gemm(
    const __nv_bfloat16* __restrict__ Xhi, const __nv_bfloat16* __restrict__ Xlo,
    const int* __restrict__ g2,
    const __nv_bfloat16* __restrict__ Whi, const __nv_bfloat16* __restrict__ Wlo,
    const float* __restrict__ Bias,
    __nv_bfloat16* __restrict__ Yhi, __nv_bfloat16* __restrict__ Ylo,
    float* __restrict__ Yf,
    const int* __restrict__ row_idx, const int* __restrict__ counts,
    int seg, int K, int Ntot, int relu, int mode)
{
    const int e   = blockIdx.y;
    const int cnt = __ldg(&counts[e]);
    const int m0  = blockIdx.x << 7;
    if (m0 >= cnt) return;
    const int n0  = blockIdx.z << 7;

    extern __shared__ char smem[];
    const uint32_t sb = s2u(smem);
    int* ridx_s = (int*)(smem + S_RIDX);
    const int tid = threadIdx.x;

    int valid = cnt - m0; if (valid > 128) valid = 128;
    if (tid < 128) {
        int mm = (tid < valid) ? tid : (valid - 1);   // clamp: duplicate rows only read
        ridx_s[tid] = __ldg(&row_idx[(size_t)e * seg + m0 + mm]);
    }
    __syncthreads();

    // ---- loader setup: thread tid loads 16B halves of row (tid>>1) for A and B
    const int lr   = tid >> 1;
    const int lo16 = (tid & 1) << 3;                 // element offset 0 or 8
    const int rL   = ridx_s[lr];
    size_t abase;
    if (mode == 2) { int b = rL / 9, p = rL - b * 9; abase = (size_t)(b * 34 + 16 + 2 * p) * 128; }
    else           abase = (size_t)rL * K;
    const size_t wbase = ((size_t)e * Ntot + n0 + lr) * K;
    const uint32_t ldst = (uint32_t)(lr * 48 + (tid & 1) * 16);

    // ---- compute setup
    const int lane = tid & 31;
    const int wm   = (tid >> 5) & 3;                 // 4 row-warps (32 rows each)
    const int wn   = tid >> 7;                       // 2 col-warps (64 cols each)
    // A: lanes 0-7 -> rows 0-7 k0 | 8-15 -> rows 8-15 k0 | 16-23 -> rows 0-7 k8 | 24-31 -> rows 8-15 k8
    const uint32_t offA = (uint32_t)((wm*32 + (lane & 7) + ((lane & 8) ? 8 : 0)) * 48 + ((lane & 16) ? 16 : 0));
    // B (non-trans on [n][k] rows): m0 = n 0-7 k 0-7 (b0), m1 = n 0-7 k 8-15 (b1),
    //                                m2 = n 8-15 k 0-7, m3 = n 8-15 k 8-15
    const uint32_t offB = (uint32_t)((wn*64 + (lane & 7) + ((lane & 16) ? 8 : 0)) * 48 + ((lane & 8) ? 16 : 0));

    float acc[2][8][4];
    #pragma unroll
    for (int i = 0; i < 2; i++)
        #pragma unroll
        for (int j = 0; j < 8; j++)
            #pragma unroll
            for (int q = 0; q < 4; q++) acc[i][j][q] = 0.f;

    const int nc = K >> 4;

    // ---- chunk loader (k16): A hi/lo + B hi/lo, 4x cp.async.16B per thread
    #define LOAD_CHUNK(c, s) do { \
        int _k0 = (c) << 4; \
        size_t _ax; \
        if (mode == 1) { \
            int _ent = __ldg(&g2[2 * rL + (_k0 >> 7)]); \
            _ax = ((size_t)_ent << 7) + (_k0 & 127); \
        } else _ax = abase + _k0; \
        cpa16(sb + ST_A(s,0) + ldst, Xhi + _ax + lo16); \
        cpa16(sb + ST_A(s,1) + ldst, Xlo + _ax + lo16); \
        cpa16(sb + ST_B(s,0) + ldst, Whi + wbase + _k0 + lo16); \
        cpa16(sb + ST_B(s,1) + ldst, Wlo + wbase + _k0 + lo16); \
        asm volatile("cp.async.commit_group;" ::: "memory"); \
    } while (0)

    LOAD_CHUNK(0, 0);
    for (int c = 0; c < nc; ++c) {
        if (c + 1 < nc) {
            LOAD_CHUNK(c + 1, (c + 1) & 1);
            asm volatile("cp.async.wait_group 1;" ::: "memory");
        } else {
            asm volatile("cp.async.wait_group 0;" ::: "memory");
        }
        __syncthreads();

        const int s = c & 1;
        const uint32_t aH = sb + ST_A(s,0), aL = sb + ST_A(s,1);
        const uint32_t bH = sb + ST_B(s,0), bL = sb + ST_B(s,1);

        uint32_t Ah0[4], Ah1[4], Al0[4], Al1[4];
        ldm_x4(Ah0, aH + offA); ldm_x4(Ah1, aH + offA + 768);
        ldm_x4(Al0, aL + offA); ldm_x4(Al1, aL + offA + 768);

        uint32_t Bh[8][2], Bl[8][2];
        #pragma unroll
        for (int q = 0; q < 4; ++q) {
            uint32_t t[4];
            ldm_x4(t, bH + offB + q * 768);   // non-trans: [n][k] storage is already col-major B
            Bh[2*q][0] = t[0]; Bh[2*q][1] = t[1]; Bh[2*q+1][0] = t[2]; Bh[2*q+1][1] = t[3];
            ldm_x4(t, bL + offB + q * 768);
            Bl[2*q][0] = t[0]; Bl[2*q][1] = t[1]; Bl[2*q+1][0] = t[2]; Bl[2*q+1][1] = t[3];
        }

        #pragma unroll
        for (int nt = 0; nt < 8; ++nt) {
            mma_bf16(acc[0][nt], Ah0, Bh[nt]);
            mma_bf16(acc[1][nt], Ah1, Bh[nt]);
            mma_bf16(acc[0][nt], Ah0, Bl[nt]);
            mma_bf16(acc[1][nt], Ah1, Bl[nt]);
            mma_bf16(acc[0][nt], Al0, Bh[nt]);
            mma_bf16(acc[1][nt], Al1, Bh[nt]);
        }
        __syncthreads();
    }
    #undef LOAD_CHUNK

    // ---- epilogue: bias + relu + hi/lo split + optional fp32, scatter to gathered rows
    const int g  = lane >> 2;
    const int tg = lane & 3;
    float2 bias2[8];
    #pragma unroll
    for (int nt = 0; nt < 8; ++nt)
        bias2[nt] = *(const float2*)(Bias + (size_t)e * Ntot + n0 + wn*64 + nt*8 + tg*2);

    #pragma unroll
    for (int mt = 0; mt < 2; ++mt) {
        #pragma unroll
        for (int rs = 0; rs < 2; ++rs) {
            int ml = wm*32 + mt*16 + g + rs*8;
            if (ml < valid) {
                int rX = ridx_s[ml];
                #pragma unroll
                for (int nt = 0; nt < 8; ++nt) {
                    float v0 = acc[mt][nt][rs*2]   + bias2[nt].x;
                    float v1 = acc[mt][nt][rs*2+1] + bias2[nt].y;
                    if (relu) { v0 = fmaxf(v0, 0.f); v1 = fmaxf(v1, 0.f); }
                    __nv_bfloat16 h0 = __float2bfloat16(v0);
                    __nv_bfloat16 h1 = __float2bfloat16(v1);
                    __nv_bfloat162 hh; hh.x = h0; hh.y = h1;
                    __nv_bfloat162 ll;
                    ll.x = __float2bfloat16(v0 - __bfloat162float(h0));
                    ll.y = __float2bfloat16(v1 - __bfloat162float(h1));
                    size_t yb = (size_t)rX * Ntot + n0 + wn*64 + nt*8 + tg*2;
                    *(uint32_t*)(Yhi + yb) = *(uint32_t*)&hh;
                    *(uint32_t*)(Ylo + yb) = *(uint32_t*)&ll;
                    if (Yf) *(float2*)(Yf + yb) = make_float2(v0, v1);
                }
            }
        }
    }
}

// ---------------- final: 3 q-projections + softmax attends + concat ----------------
__global__ void k_finale(const float* __restrict__ roots, const float* __restrict__ stmt,
                         const float* __restrict__ th_emb, const int* __restrict__ th_idx,
                         const float* __restrict__ heW, const float* __restrict__ heb,
                         const float* __restrict__ hgW, const float* __restrict__ hgb,
                         const float* __restrict__ htW, const float* __restrict__ htb,
                         float* __restrict__ out)
{
    __shared__ float obj[128];
    __shared__ float q[128];
    __shared__ float keys[16][128];
    __shared__ float aw[16];
    const int b = blockIdx.x;
    const int t = threadIdx.x;

    float ov = stmt[(size_t)(b * 9 + 8) * 128 + t];
    obj[t] = ov;
    out[(size_t)b * 512 + t] = ov;
    __syncthreads();

    const float* Wq[3] = {heW, hgW, htW};
    const float* bq[3] = {heb, hgb, htb};
    const int    nk[3] = {16, 8, 8};
    const int    oo[3] = {256, 128, 384};

    for (int s = 0; s < 3; s++) {
        float accq = bq[s][t];
        const float* w = Wq[s];
        #pragma unroll 4
        for (int k = 0; k < 128; k++) accq = fmaf(obj[k], w[k * 128 + t], accq);
        q[t] = accq;
        if (s == 0) {
            for (int j = 0; j < 16; j++) keys[j][t] = roots[(size_t)(b * 34 + j) * 128 + t];
        } else if (s == 1) {
            for (int j = 0; j < 8; j++)  keys[j][t] = stmt[(size_t)(b * 9 + j) * 128 + t];
        } else {
            for (int j = 0; j < 8; j++)  keys[j][t] = th_emb[(size_t)th_idx[b * 8 + j] * 128 + t];
        }
        __syncthreads();
        int n = nk[s];
        if (t < n) {
            float sdot = 0.f;
            for (int k = 0; k < 128; k++) sdot = fmaf(keys[t][k], q[k], sdot);
            aw[t] = sdot;
        }
        __syncthreads();
        if (t == 0) {
            float mx = aw[0];
            for (int j = 1; j < n; j++) mx = fmaxf(mx, aw[j]);
            float sm = 0.f;
            for (int j = 0; j < n; j++) { float ev = expf(aw[j] - mx); aw[j] = ev; sm += ev; }
            float inv = 1.f / sm;
            for (int j = 0; j < n; j++) aw[j] *= inv;
        }
        __syncthreads();
        float ctx = 0.f;
        for (int j = 0; j < n; j++) ctx = fmaf(aw[j], keys[j][t], ctx);
        out[(size_t)b * 512 + oo[s] + t] = ctx;
        __syncthreads();
    }
}

// ---------------- launch ----------------
#define GETSYM(var, sym) { void* _p; cudaGetSymbolAddress(&_p, sym); var = decltype(var)(_p); }

extern "C" void kernel_launch(void* const* d_in, const int* in_sizes, int n_in,
                              void* d_out, int out_size)
{
    const int*   leaf_idx = (const int*)  d_in[0];
    const int*   nf_ids   = (const int*)  d_in[1];
    const int*   lf_ids   = (const int*)  d_in[2];
    const int*   th_idx   = (const int*)  d_in[3];
    const float* ent_emb  = (const float*)d_in[4];
    const float* th_emb   = (const float*)d_in[5];
    const float* nfW1     = (const float*)d_in[6];
    const float* nfb1     = (const float*)d_in[7];
    const float* nfW2     = (const float*)d_in[8];
    const float* nfb2     = (const float*)d_in[9];
    const float* lfW1     = (const float*)d_in[10];
    const float* lfb1     = (const float*)d_in[11];
    const float* lfW2     = (const float*)d_in[12];
    const float* lfb2     = (const float*)d_in[13];
    const float* heW      = (const float*)d_in[14];
    const float* heb      = (const float*)d_in[15];
    const float* hgW      = (const float*)d_in[16];
    const float* hgb      = (const float*)d_in[17];
    const float* htW      = (const float*)d_in[18];
    const float* htb      = (const float*)d_in[19];
    float* out = (float*)d_out;

    __nv_bfloat16 *Hhi, *Hlo, *o0hi, *o0lo, *o1hi, *o1lo, *o2hi, *o2lo;
    __nv_bfloat16 *rthi, *rtlo, *sthi, *stlo, *ehi, *elo;
    __nv_bfloat16 *w1hi, *w1lo, *w2hi, *w2lo, *l1hi, *l1lo, *l2hi, *l2lo;
    float *roots, *stmt;
    int *idx, *cnt;
    GETSYM(Hhi, g_Hhi);  GETSYM(Hlo, g_Hlo);
    GETSYM(o0hi, g_o0hi); GETSYM(o0lo, g_o0lo);
    GETSYM(o1hi, g_o1hi); GETSYM(o1lo, g_o1lo);
    GETSYM(o2hi, g_o2hi); GETSYM(o2lo, g_o2lo);
    GETSYM(rthi, g_rthi); GETSYM(rtlo, g_rtlo);
    GETSYM(sthi, g_sthi); GETSYM(stlo, g_stlo);
    GETSYM(ehi, g_ehi);   GETSYM(elo, g_elo);
    GETSYM(w1hi, g_w1hi); GETSYM(w1lo, g_w1lo);
    GETSYM(w2hi, g_w2hi); GETSYM(w2lo, g_w2lo);
    GETSYM(l1hi, g_l1hi); GETSYM(l1lo, g_l1lo);
    GETSYM(l2hi, g_l2hi); GETSYM(l2lo, g_l2lo);
    GETSYM(roots, g_roots); GETSYM(stmt, g_stmt);
    GETSYM(idx, g_idx);   GETSYM(cnt, g_counts);

    cudaFuncSetAttribute(k_mma_gemm, cudaFuncAttributeMaxDynamicSharedMemorySize, SMEM_BYTES);

    // 1) counters + per-expert row lists
    k_zero_counts<<<1, 32>>>(cnt);
    k_build_idx<<<R0 / 256, 256>>>(nf_ids, R0, 8, 0,  15, cnt + 0,  idx + IDX0, R0, 4);
    k_build_idx<<<R1 / 256, 256>>>(nf_ids, R1, 4, 8,  15, cnt + 4,  idx + IDX1, R1, 4);
    k_build_idx<<<R2 / 256, 256>>>(nf_ids, R2, 2, 12, 15, cnt + 8,  idx + IDX2, R2, 4);
    k_build_idx<<<R3 / 256, 256>>>(nf_ids, R3, 1, 14, 15, cnt + 12, idx + IDX3, R3, 4);
    k_build_idx<<<RF / 256, 256>>>(lf_ids, RF, 9, 0,  9,  cnt + 16, idx + IDXF, RF, 3);

    // 2) pre-split embeddings + transposed split weights
    k_split<<<(2000 * 128 + 255) / 256, 256>>>(ent_emb, ehi, elo, 2000 * 128);
    k_prep_w<<<(4 * 256 * 256 + 255) / 256, 256>>>(nfW1, w1hi, w1lo, 256, 256, 4 * 256 * 256);
    k_prep_w<<<(4 * 256 * 128 + 255) / 256, 256>>>(nfW2, w2hi, w2lo, 256, 128, 4 * 256 * 128);
    k_prep_w<<<(3 * 256 * 512 + 255) / 256, 256>>>(lfW1, l1hi, l1lo, 256, 512, 3 * 256 * 512);
    k_prep_w<<<(3 * 512 * 128 + 255) / 256, 256>>>(lfW2, l2hi, l2lo, 512, 128, 3 * 512 * 128);

    // 3) tree levels on tensor cores (layer1 relu -> H, layer2 -> level output)
    k_mma_gemm<<<dim3(R0/128, 4, 2), 256, SMEM_BYTES>>>(ehi, elo, leaf_idx, w1hi, w1lo, nfb1,
        Hhi, Hlo, nullptr, idx+IDX0, cnt+0, R0, 256, 256, 1, 1);
    k_mma_gemm<<<dim3(R0/128, 4, 1), 256, SMEM_BYTES>>>(Hhi, Hlo, nullptr, w2hi, w2lo, nfb2,
        o0hi, o0lo, nullptr, idx+IDX0, cnt+0, R0, 256, 128, 0, 0);
    k_mma_gemm<<<dim3(R1/128, 4, 2), 256, SMEM_BYTES>>>(o0hi, o0lo, nullptr, w1hi, w1lo, nfb1,
        Hhi, Hlo, nullptr, idx+IDX1, cnt+4, R1, 256, 256, 1, 0);
    k_mma_gemm<<<dim3(R1/128, 4, 1), 256, SMEM_BYTES>>>(Hhi, Hlo, nullptr, w2hi, w2lo, nfb2,
        o1hi, o1lo, nullptr, idx+IDX1, cnt+4, R1, 256, 128, 0, 0);
    k_mma_gemm<<<dim3(R2/128, 4, 2), 256, SMEM_BYTES>>>(o1hi, o1lo, nullptr, w1hi, w1lo, nfb1,
        Hhi, Hlo, nullptr, idx+IDX2, cnt+8, R2, 256, 256, 1, 0);
    k_mma_gemm<<<dim3(R2/128, 4, 1), 256, SMEM_BYTES>>>(Hhi, Hlo, nullptr, w2hi, w2lo, nfb2,
        o2hi, o2lo, nullptr, idx+IDX2, cnt+8, R2, 256, 128, 0, 0);
    k_mma_gemm<<<dim3(R3/128, 4, 2), 256, SMEM_BYTES>>>(o2hi, o2lo, nullptr, w1hi, w1lo, nfb1,
        Hhi, Hlo, nullptr, idx+IDX3, cnt+12, R3, 256, 256, 1, 0);
    k_mma_gemm<<<dim3(R3/128, 4, 1), 256, SMEM_BYTES>>>(Hhi, Hlo, nullptr, w2hi, w2lo, nfb2,
        rthi, rtlo, roots, idx+IDX3, cnt+12, R3, 256, 128, 0, 0);

    // 4) statement MLP on root pairs (pair-map view into roots hi/lo)
    k_mma_gemm<<<dim3(RF/128, 3, 4), 256, SMEM_BYTES>>>(rthi, rtlo, nullptr, l1hi, l1lo, lfb1,
        Hhi, Hlo, nullptr, idx+IDXF, cnt+16, RF, 256, 512, 1, 2);
    k_mma_gemm<<<dim3(RF/128, 3, 1), 256, SMEM_BYTES>>>(Hhi, Hlo, nullptr, l2hi, l2lo, lfb2,
        sthi, stlo, stmt, idx+IDXF, cnt+16, RF, 512, 128, 0, 0);

    // 5) attention heads + concat
    k_finale<<<BATCH, 128>>>(roots, stmt, th_emb, th_idx, heW, heb, hgW, hgb, htW, htb, out);
}